// round 7
// baseline (speedup 1.0000x reference)
#include <cuda_runtime.h>

// RNN: B=4096, T=1024, H=64, scalar input, C=5 head.
//   h_{t+1}[b,i] = tanh(x[b,t]*w_ih[i] + b_ih[i] + b_hh[i] + sum_j h_t[b,j]*w_hh[i,j])
//   out[b,c]     = sum_j hT[b,j]*w_head[c,j] + b_head[c]
//
// R6 design: 512 threads / 16 warps (4 per SMSP). Warp-pairs share 4 batches:
// even warp computes rows 0-31 (1 row per lane), odd warp rows 32-63.
// W_hh row in registers (64 regs/lane), h broadcast-loaded from SMEM,
// f32x2 packed along j, pairwise named-barrier sync (no CTA barrier in loop).

#define BB 4096
#define TT 1024
#define HH 64
#define CC 5
#define NB 32            // batches per CTA
#define NTHREADS 512     // 16 warps, 8 pairs
#define BPP 4            // batches per warp-pair

typedef unsigned long long u64;

__device__ __forceinline__ u64 fma2(u64 a, u64 b, u64 c) {
    u64 d; asm("fma.rn.f32x2 %0, %1, %2, %3;" : "=l"(d) : "l"(a), "l"(b), "l"(c)); return d;
}
__device__ __forceinline__ float2 up2(u64 v) {
    float2 f; asm("mov.b64 {%0,%1}, %2;" : "=f"(f.x), "=f"(f.y) : "l"(v)); return f;
}
__device__ __forceinline__ float ftanh(float xv) {
    // tanh(x) = 1 - 2/(e^{2x}+1); exact at saturation via inf.
    float e = __expf(2.0f * xv);
    return 1.0f - __fdividef(2.0f, e + 1.0f);
}
__device__ __forceinline__ void bar_pair(int id) {
    asm volatile("bar.sync %0, 64;" :: "r"(id) : "memory");
}

extern "C" __global__ void __launch_bounds__(NTHREADS, 1)
rnn_pair_kernel(const float* __restrict__ x,
                const float* __restrict__ w_ih,
                const float* __restrict__ b_ih,
                const float* __restrict__ w_hh,
                const float* __restrict__ b_hh,
                const float* __restrict__ w_head,
                const float* __restrict__ b_head,
                float* __restrict__ out)
{
    __shared__ __align__(16) float hs[2][NB][HH];   // 16 KB, double-buffered h

    const int tid  = threadIdx.x;
    const int lane = tid & 31;
    const int wrp  = tid >> 5;
    const int pair = wrp >> 1;                  // 0..7
    const int half = wrp & 1;                   // 0: rows 0-31, 1: rows 32-63
    const int b0   = pair * BPP;                // local batch base (pair-private)
    const int gb   = blockIdx.x * NB + b0;      // global batch base
    const int row  = half * 32 + lane;          // this lane's output row

    // --- W_hh row `row` into registers, packed as j-pairs (64 regs) ---
    u64 wreg[32];
    {
        const u64* wr = (const u64*)(w_hh + (size_t)row * HH);
#pragma unroll
        for (int jp = 0; jp < 32; jp++) wreg[jp] = wr[jp];
    }
    const float wihv = w_ih[row];
    const float biav = b_ih[row] + b_hh[row];

    // --- zero h buffer 0 for this pair's batches (64 thr x 4 floats) ---
#pragma unroll
    for (int k = 0; k < BPP; k++)
        hs[0][b0 + k][row] = 0.0f;

    // --- x chunks: lane holds x[b][t0+lane]; prefetch 32 steps ahead ---
    float xcur[BPP], xnxt[BPP];
#pragma unroll
    for (int k = 0; k < BPP; k++) xnxt[k] = x[(size_t)(gb + k) * TT + lane];

    bar_pair(pair);

    int cur = 0;
    for (int t = 0; t < TT; t++) {
        const int tc = t & 31;
        if (tc == 0) {
#pragma unroll
            for (int k = 0; k < BPP; k++) xcur[k] = xnxt[k];
            if (t + 32 < TT) {
#pragma unroll
                for (int k = 0; k < BPP; k++)
                    xnxt[k] = x[(size_t)(gb + k) * TT + (t + 32) + lane];
            }
        }

        const ulonglong2* hb0 = (const ulonglong2*)hs[cur][b0 + 0];
        const ulonglong2* hb1 = (const ulonglong2*)hs[cur][b0 + 1];
        const ulonglong2* hb2 = (const ulonglong2*)hs[cur][b0 + 2];
        const ulonglong2* hb3 = (const ulonglong2*)hs[cur][b0 + 3];

        u64 acc[BPP];
#pragma unroll
        for (int k = 0; k < BPP; k++) acc[k] = 0ull;

#pragma unroll
        for (int q = 0; q < 16; q++) {
            // broadcast loads: all lanes read the same 16B => 1 wavefront each
            ulonglong2 h0 = hb0[q];
            ulonglong2 h1 = hb1[q];
            ulonglong2 h2 = hb2[q];
            ulonglong2 h3 = hb3[q];
            const u64 wa = wreg[2*q], wb = wreg[2*q + 1];
            acc[0] = fma2(wa, h0.x, acc[0]);
            acc[1] = fma2(wa, h1.x, acc[1]);
            acc[2] = fma2(wa, h2.x, acc[2]);
            acc[3] = fma2(wa, h3.x, acc[3]);
            acc[0] = fma2(wb, h0.y, acc[0]);
            acc[1] = fma2(wb, h1.y, acc[1]);
            acc[2] = fma2(wb, h2.y, acc[2]);
            acc[3] = fma2(wb, h3.y, acc[3]);
        }

        // epilogue: horizontal add + input/bias + tanh + coalesced store
        float* hn = (float*)hs[cur ^ 1];
#pragma unroll
        for (int k = 0; k < BPP; k++) {
            float xv = __shfl_sync(0xffffffffu, xcur[k], tc);
            float2 a = up2(acc[k]);
            float s = a.x + a.y + fmaf(xv, wihv, biav);
            hn[(b0 + k) * HH + row] = ftanh(s);
        }
        bar_pair(pair);
        cur ^= 1;
    }

    // --- head: out[b,c] = sum_j h[b,j]*w_head[c,j] + b_head[c] ---
    // even warp of each pair: lanes 0..19 -> (batch k, class c)
    if (half == 0 && lane < BPP * CC) {
        const int k = lane / CC;
        const int c = lane % CC;
        const float* hf = hs[cur][b0 + k];
        float s = b_head[c];
#pragma unroll
        for (int j = 0; j < HH; j++)
            s = fmaf(hf[j], w_head[c * HH + j], s);
        out[(size_t)(gb + k) * CC + c] = s;
    }
}

extern "C" void kernel_launch(void* const* d_in, const int* in_sizes, int n_in,
                              void* d_out, int out_size)
{
    (void)in_sizes; (void)n_in; (void)out_size;
    const float* x      = (const float*)d_in[0];
    const float* w_ih   = (const float*)d_in[1];
    const float* b_ih   = (const float*)d_in[2];
    const float* w_hh   = (const float*)d_in[3];
    const float* b_hh   = (const float*)d_in[4];
    const float* w_head = (const float*)d_in[5];
    const float* b_head = (const float*)d_in[6];
    float* out = (float*)d_out;

    rnn_pair_kernel<<<BB / NB, NTHREADS>>>(
        x, w_ih, b_ih, w_hh, b_hh, w_head, b_head, out);
}

// round 8
// speedup vs baseline: 1.2365x; 1.2365x over previous
#include <cuda_runtime.h>

// RNN: B=4096, T=1024, H=64, scalar input, C=5 head.
//   h_{t+1}[b,i] = tanh(x[b,t]*w_ih[i] + b_ih[i] + b_hh[i] + sum_j h_t[b,j]*w_hh[i,j])
//   out[b,c]     = sum_j hT[b,j]*w_head[c,j] + b_head[c]
//
// R7 = R5 (best: warp-private batches, W in regs, broadcast h loads) +
// anti-phase skew: odd warps burn a ~550-cycle dependent-FMA preamble once,
// so the two warps sharing each SMSP run half-a-step out of phase forever
// (no inter-warp sync exists to re-align them). Warp A's serial tail
// (tanh/STS/syncwarp/LDS) then overlaps warp B's fma2 phase.

#define BB 4096
#define TT 1024
#define HH 64
#define CC 5
#define NB 32            // batches per CTA
#define NTHREADS 256     // 8 warps
#define BPW 4            // batches per warp
#define SKEW_FMA 144     // dependent FFMA chain, ~576 cyc

typedef unsigned long long u64;

__device__ __forceinline__ u64 fma2(u64 a, u64 b, u64 c) {
    u64 d; asm("fma.rn.f32x2 %0, %1, %2, %3;" : "=l"(d) : "l"(a), "l"(b), "l"(c)); return d;
}
__device__ __forceinline__ float2 up2(u64 v) {
    float2 f; asm("mov.b64 {%0,%1}, %2;" : "=f"(f.x), "=f"(f.y) : "l"(v)); return f;
}
__device__ __forceinline__ float ftanh(float xv) {
    // tanh(x) = 1 - 2/(e^{2x}+1); exact at saturation via inf.
    float e = __expf(2.0f * xv);
    return 1.0f - __fdividef(2.0f, e + 1.0f);
}

extern "C" __global__ void __launch_bounds__(NTHREADS, 1)
rnn_skew_kernel(const float* __restrict__ x,
                const float* __restrict__ w_ih,
                const float* __restrict__ b_ih,
                const float* __restrict__ w_hh,
                const float* __restrict__ b_hh,
                const float* __restrict__ w_head,
                const float* __restrict__ b_head,
                float* __restrict__ out)
{
    __shared__ __align__(16) float hs[2][NB][HH];   // 16 KB, double-buffered h

    const int tid  = threadIdx.x;
    const int lane = tid & 31;
    const int wrp  = tid >> 5;
    const int b0   = wrp * BPW;                  // local batch base (warp-private)
    const int gb   = blockIdx.x * NB + b0;       // global batch base
    const int row0 = lane;
    const int row1 = lane + 32;

    // --- W_hh rows {lane, lane+32} into registers, packed as j-pairs ---
    u64 wreg0[32], wreg1[32];
    {
        const u64* wr0 = (const u64*)(w_hh + (size_t)row0 * HH);
        const u64* wr1 = (const u64*)(w_hh + (size_t)row1 * HH);
#pragma unroll
        for (int jp = 0; jp < 32; jp++) { wreg0[jp] = wr0[jp]; wreg1[jp] = wr1[jp]; }
    }
    const float wih0 = w_ih[row0], wih1 = w_ih[row1];
    const float bia0 = b_ih[row0] + b_hh[row0];
    const float bia1 = b_ih[row1] + b_hh[row1];

    // --- zero h buffer 0 for this warp's batches ---
#pragma unroll
    for (int k = 0; k < BPW; k++) {
        hs[0][b0 + k][row0] = 0.0f;
        hs[0][b0 + k][row1] = 0.0f;
    }
    __syncwarp();

    // --- anti-phase skew: odd warps run a latency-bound dependent FMA chain
    //     (~4 cyc/link, ~SKEW_FMA*4 cycles, negligible pipe occupancy) ---
    if (wrp & 1) {
        float z = bia0 + 1.0f;
#pragma unroll
        for (int i = 0; i < SKEW_FMA; i++)
            asm volatile("fma.rn.f32 %0, %0, %1, %2;"
                         : "+f"(z) : "f"(0.9999999f), "f"(1e-30f));
        // never true, but keeps the chain alive against DCE
        if (z == -123456.75f) hs[0][b0][row0] = z;
    }

    // --- x chunking: lane holds x[b][t0+lane]; prefetch next chunk ---
    float xcur[BPW], xnxt[BPW];
#pragma unroll
    for (int k = 0; k < BPW; k++) xnxt[k] = x[(size_t)(gb + k) * TT + lane];

    int cur = 0;
    for (int t = 0; t < TT; t++) {
        const int tc = t & 31;
        if (tc == 0) {
#pragma unroll
            for (int k = 0; k < BPW; k++) xcur[k] = xnxt[k];
            if (t + 32 < TT) {
#pragma unroll
                for (int k = 0; k < BPW; k++)
                    xnxt[k] = x[(size_t)(gb + k) * TT + (t + 32) + lane];
            }
        }

        const ulonglong2* hb0 = (const ulonglong2*)hs[cur][b0 + 0];
        const ulonglong2* hb1 = (const ulonglong2*)hs[cur][b0 + 1];
        const ulonglong2* hb2 = (const ulonglong2*)hs[cur][b0 + 2];
        const ulonglong2* hb3 = (const ulonglong2*)hs[cur][b0 + 3];

        // independent of the acc chains: base = x*w_ih + bias, per row/batch
        float base0[BPW], base1[BPW];
#pragma unroll
        for (int k = 0; k < BPW; k++) {
            float xv = __shfl_sync(0xffffffffu, xcur[k], tc);
            base0[k] = fmaf(xv, wih0, bia0);
            base1[k] = fmaf(xv, wih1, bia1);
        }

        u64 acc0[BPW], acc1[BPW];
#pragma unroll
        for (int k = 0; k < BPW; k++) { acc0[k] = 0ull; acc1[k] = 0ull; }

#pragma unroll
        for (int q = 0; q < 16; q++) {
            // broadcast loads: all lanes read the same 16B of h
            ulonglong2 h0 = hb0[q];
            ulonglong2 h1 = hb1[q];
            ulonglong2 h2 = hb2[q];
            ulonglong2 h3 = hb3[q];
            const u64 wa0 = wreg0[2*q], wb0 = wreg0[2*q + 1];
            const u64 wa1 = wreg1[2*q], wb1 = wreg1[2*q + 1];
            acc0[0] = fma2(wa0, h0.x, acc0[0]);
            acc0[1] = fma2(wa0, h1.x, acc0[1]);
            acc0[2] = fma2(wa0, h2.x, acc0[2]);
            acc0[3] = fma2(wa0, h3.x, acc0[3]);
            acc1[0] = fma2(wa1, h0.x, acc1[0]);
            acc1[1] = fma2(wa1, h1.x, acc1[1]);
            acc1[2] = fma2(wa1, h2.x, acc1[2]);
            acc1[3] = fma2(wa1, h3.x, acc1[3]);
            acc0[0] = fma2(wb0, h0.y, acc0[0]);
            acc0[1] = fma2(wb0, h1.y, acc0[1]);
            acc0[2] = fma2(wb0, h2.y, acc0[2]);
            acc0[3] = fma2(wb0, h3.y, acc0[3]);
            acc1[0] = fma2(wb1, h0.y, acc1[0]);
            acc1[1] = fma2(wb1, h1.y, acc1[1]);
            acc1[2] = fma2(wb1, h2.y, acc1[2]);
            acc1[3] = fma2(wb1, h3.y, acc1[3]);
        }

        // epilogue: horizontal add + tanh + coalesced store
        float* hn = (float*)hs[cur ^ 1];
#pragma unroll
        for (int k = 0; k < BPW; k++) {
            float2 a0 = up2(acc0[k]);
            float2 a1 = up2(acc1[k]);
            float s0 = a0.x + a0.y + base0[k];
            float s1 = a1.x + a1.y + base1[k];
            hn[(b0 + k) * HH + row0] = ftanh(s0);
            hn[(b0 + k) * HH + row1] = ftanh(s1);
        }
        __syncwarp();
        cur ^= 1;
    }

    // --- head: out[b,c] = sum_j h[b,j]*w_head[c,j] + b_head[c] ---
    if (lane < BPW * CC) {
        const int k = lane / CC;
        const int c = lane % CC;
        const float* hf = hs[cur][b0 + k];
        float s = b_head[c];
#pragma unroll
        for (int j = 0; j < HH; j++)
            s = fmaf(hf[j], w_head[c * HH + j], s);
        out[(size_t)(gb + k) * CC + c] = s;
    }
}

extern "C" void kernel_launch(void* const* d_in, const int* in_sizes, int n_in,
                              void* d_out, int out_size)
{
    (void)in_sizes; (void)n_in; (void)out_size;
    const float* x      = (const float*)d_in[0];
    const float* w_ih   = (const float*)d_in[1];
    const float* b_ih   = (const float*)d_in[2];
    const float* w_hh   = (const float*)d_in[3];
    const float* b_hh   = (const float*)d_in[4];
    const float* w_head = (const float*)d_in[5];
    const float* b_head = (const float*)d_in[6];
    float* out = (float*)d_out;

    rnn_skew_kernel<<<BB / NB, NTHREADS>>>(
        x, w_ih, b_ih, w_hh, b_hh, w_head, b_head, out);
}